// round 1
// baseline (speedup 1.0000x reference)
#include <cuda_runtime.h>

// Problem constants (fixed by the benchmark's setup_inputs)
#define BB 4
#define DD 1024
#define NN 2048
static const long PER = (long)BB * DD * NN;           // 8,388,608 elems per tensor
static const long SMAT = (long)NN * NN;               // 4,194,304 elems per score matrix

// 64 MB scratch for scores/attn (static __device__ global: allowed)
__device__ float g_scores[(size_t)BB * (size_t)NN * (size_t)NN];

// ---------------------------------------------------------------------------
// Register-blocked SGEMM: C[M][Nc] = A op B, 128x128 tile, BK=16, 256 threads,
// 8x8 per-thread microtile.
//  TRANS_A = false:  A is [M][K] row-major (lda = row stride)
//  TRANS_A = true :  A is [K][M] row-major (lda = row stride), C = A^T * B
//  B is always [K][Nc] row-major.
// Batched over gridDim.z with element strides sA/sB/sC (sA may be 0 = shared W).
// ---------------------------------------------------------------------------
template <bool TRANS_A>
__global__ __launch_bounds__(256)
void gemm128(const float* __restrict__ Ag, const float* __restrict__ Bg,
             float* __restrict__ Cg,
             int M, int Nc, int K, int lda, int ldb, int ldc,
             long sA, long sB, long sC)
{
    __shared__ float As[16][132];   // As[k][m], padded
    __shared__ float Bs[16][132];   // Bs[k][n], padded

    const float* A = Ag + (long)blockIdx.z * sA;
    const float* Bm = Bg + (long)blockIdx.z * sB;
    float* C = Cg + (long)blockIdx.z * sC;

    const int tid = threadIdx.x;
    const int tx = tid & 15;        // 0..15 -> n micro
    const int ty = tid >> 4;        // 0..15 -> m micro
    const int m0 = blockIdx.y * 128;
    const int n0 = blockIdx.x * 128;

    float acc[8][8];
#pragma unroll
    for (int i = 0; i < 8; i++)
#pragma unroll
        for (int j = 0; j < 8; j++) acc[i][j] = 0.0f;

    for (int k0 = 0; k0 < K; k0 += 16) {
        // ---- load A tile into As[k][m] ----
        if (TRANS_A) {
            // A[k][m], m contiguous: direct coalesced float4 copy
            int idx = tid;
#pragma unroll
            for (int r = 0; r < 2; r++, idx += 256) {
                int kk = idx >> 5;          // 0..15
                int cq = idx & 31;          // 0..31 -> 4 floats each
                float4 v = *(const float4*)(A + (long)(k0 + kk) * lda + m0 + 4 * cq);
                *(float4*)&As[kk][4 * cq] = v;
            }
        } else {
            // A[m][k], k contiguous: read float4 along k, scatter transposed
            int idx = tid;
#pragma unroll
            for (int r = 0; r < 2; r++, idx += 256) {
                int row = idx >> 2;         // 0..127 (m)
                int kq  = idx & 3;          // 0..3   (k quad)
                float4 v = *(const float4*)(A + (long)(m0 + row) * lda + k0 + 4 * kq);
                As[4 * kq + 0][row] = v.x;
                As[4 * kq + 1][row] = v.y;
                As[4 * kq + 2][row] = v.z;
                As[4 * kq + 3][row] = v.w;
            }
        }
        // ---- load B tile into Bs[k][n] (n contiguous) ----
        {
            int idx = tid;
#pragma unroll
            for (int r = 0; r < 2; r++, idx += 256) {
                int kk = idx >> 5;
                int cq = idx & 31;
                float4 v = *(const float4*)(Bm + (long)(k0 + kk) * ldb + n0 + 4 * cq);
                *(float4*)&Bs[kk][4 * cq] = v;
            }
        }
        __syncthreads();

        // ---- compute ----
#pragma unroll
        for (int k = 0; k < 16; k++) {
            float ar[8], br[8];
#pragma unroll
            for (int i = 0; i < 8; i++) ar[i] = As[k][ty * 8 + i];
#pragma unroll
            for (int j = 0; j < 8; j++) br[j] = Bs[k][tx * 8 + j];
#pragma unroll
            for (int i = 0; i < 8; i++)
#pragma unroll
                for (int j = 0; j < 8; j++)
                    acc[i][j] += ar[i] * br[j];
        }
        __syncthreads();
    }

    // ---- epilogue: float4 stores ----
#pragma unroll
    for (int i = 0; i < 8; i++) {
        float* cp = C + (long)(m0 + ty * 8 + i) * ldc + n0 + tx * 8;
        *(float4*)cp       = make_float4(acc[i][0], acc[i][1], acc[i][2], acc[i][3]);
        *(float4*)(cp + 4) = make_float4(acc[i][4], acc[i][5], acc[i][6], acc[i][7]);
    }
}

// ---------------------------------------------------------------------------
// Batch-axis softmax (+ scale + hard mask), in place over g_scores.
// attn[b,i,j] = softmax over b of (scores[b,i,j]/32, masked quadrant -> -1e12)
// Masked quadrant yields exactly 0.25 per batch (matches reference).
// ---------------------------------------------------------------------------
__global__ void softmax_batch_kernel(const int* __restrict__ mask_from_p,
                                     float* __restrict__ S)
{
    long idx = (long)blockIdx.x * blockDim.x + threadIdx.x;
    if (idx >= SMAT) return;
    const int j = (int)(idx & (NN - 1));
    const int i = (int)(idx >> 11);       // NN = 2048 = 2^11
    const int mf = *mask_from_p;
    const float scale = 0.03125f;          // 1/sqrt(1024)

    float s0 = S[idx]             * scale;
    float s1 = S[idx + SMAT]      * scale;
    float s2 = S[idx + 2 * SMAT]  * scale;
    float s3 = S[idx + 3 * SMAT]  * scale;

    if (i >= mf && j >= mf) {
        s0 = s1 = s2 = s3 = -1.0e12f;
    }
    float m = fmaxf(fmaxf(s0, s1), fmaxf(s2, s3));
    float e0 = expf(s0 - m);
    float e1 = expf(s1 - m);
    float e2 = expf(s2 - m);
    float e3 = expf(s3 - m);
    float inv = 1.0f / (e0 + e1 + e2 + e3);

    S[idx]            = e0 * inv;
    S[idx + SMAT]     = e1 * inv;
    S[idx + 2 * SMAT] = e2 * inv;
    S[idx + 3 * SMAT] = e3 * inv;
}

// ---------------------------------------------------------------------------
// kernel_launch: out layout = [out | Q | K | V], each [B, d, n] fp32.
// ---------------------------------------------------------------------------
extern "C" void kernel_launch(void* const* d_in, const int* in_sizes, int n_in,
                              void* d_out, int out_size)
{
    (void)in_sizes; (void)n_in; (void)out_size;
    const float* x   = (const float*)d_in[0];
    const float* W_q = (const float*)d_in[1];
    const float* W_k = (const float*)d_in[2];
    const float* W_v = (const float*)d_in[3];
    const int* mask_from = (const int*)d_in[4];

    float* out = (float*)d_out;            // [B,d,n]
    float* Q   = out + PER;                // [B,d,n]
    float* K   = out + 2 * PER;
    float* V   = out + 3 * PER;

    float* scores;
    cudaGetSymbolAddress((void**)&scores, g_scores);

    // 1) QKV projections: C[b] = W @ x[b].  M=d, N=n, K=d.
    {
        dim3 grid(NN / 128, DD / 128, BB);
        gemm128<false><<<grid, 256>>>(W_q, x, Q, DD, NN, DD, DD, NN, NN,
                                      0, (long)DD * NN, (long)DD * NN);
        gemm128<false><<<grid, 256>>>(W_k, x, K, DD, NN, DD, DD, NN, NN,
                                      0, (long)DD * NN, (long)DD * NN);
        gemm128<false><<<grid, 256>>>(W_v, x, V, DD, NN, DD, DD, NN, NN,
                                      0, (long)DD * NN, (long)DD * NN);
    }

    // 2) scores[b] = Q[b]^T K[b].  Both stored [d][n] (n contiguous) -> TRANS_A.
    //    M = n, N = n, K = d, lda = ldb = n.
    {
        dim3 grid(NN / 128, NN / 128, BB);
        gemm128<true><<<grid, 256>>>(Q, K, scores, NN, NN, DD, NN, NN, NN,
                                     (long)DD * NN, (long)DD * NN, SMAT);
    }

    // 3) batch-axis softmax + scale + mask, in place.
    {
        long total = SMAT;
        int threads = 256;
        long blocks = (total + threads - 1) / threads;
        softmax_batch_kernel<<<(unsigned)blocks, threads>>>(mask_from, scores);
    }

    // 4) out[b] = V[b] @ attn[b].  M=d, N=n, K=n.
    {
        dim3 grid(NN / 128, DD / 128, BB);
        gemm128<false><<<grid, 256>>>(V, scores, out, DD, NN, NN, NN, NN, NN,
                                      (long)DD * NN, SMAT, (long)DD * NN);
    }
}

// round 4
// speedup vs baseline: 2.6193x; 2.6193x over previous
#include <cuda_runtime.h>
#include <cuda_bf16.h>
#include <cstdint>

// ---------------------------------------------------------------------------
// Problem constants (fixed by setup_inputs)
// ---------------------------------------------------------------------------
#define BB 4
#define DDIM 1024
#define NTOK 2048
static const long DN   = (long)DDIM * NTOK;        // 2,097,152 elems
static const long PER  = (long)BB * DN;            // 8,388,608 elems per tensor
static const long SMAT = (long)NTOK * NTOK;        // 4,194,304 elems per score mat

// ---------------------------------------------------------------------------
// Static device scratch (allocation-rule-safe). ~268 MB total.
// ---------------------------------------------------------------------------
__device__ __align__(1024) float         g_scores[(size_t)BB * NTOK * NTOK];      // 64MB
__device__ __align__(1024) __nv_bfloat16 g_xT[2][(size_t)BB * NTOK * DDIM];       // x^T hi/lo [b][n][d]
__device__ __align__(1024) __nv_bfloat16 g_W [2][(size_t)3 * DDIM * DDIM];        // Wq|Wk|Wv hi/lo
__device__ __align__(1024) __nv_bfloat16 g_Qt[2][(size_t)BB * NTOK * DDIM];       // Q^T hi/lo
__device__ __align__(1024) __nv_bfloat16 g_Kt[2][(size_t)BB * NTOK * DDIM];       // K^T hi/lo
__device__ __align__(1024) __nv_bfloat16 g_V [2][(size_t)BB * DDIM * NTOK];       // V hi/lo
__device__ __align__(1024) __nv_bfloat16 g_At[2][(size_t)BB * NTOK * NTOK];       // attn^T hi/lo

// ---------------------------------------------------------------------------
// PTX helpers — ONLY sm_80-era instructions (cp.async, ldmatrix, mma.sync).
// No tcgen05 anywhere (ptxas target is plain sm_100, no 'a' features).
// ---------------------------------------------------------------------------
__device__ __forceinline__ uint32_t smem_u32(const void* p) {
    uint32_t a;
    asm("{ .reg .u64 t; cvta.to.shared.u64 t, %1; cvt.u32.u64 %0, t; }" : "=r"(a) : "l"(p));
    return a;
}
__device__ __forceinline__ void cp16(uint32_t dst, const void* src) {
    asm volatile("cp.async.cg.shared.global [%0], [%1], 16;" :: "r"(dst), "l"(src));
}
__device__ __forceinline__ void cp_commit() { asm volatile("cp.async.commit_group;" ::: "memory"); }
__device__ __forceinline__ void cp_wait0()  { asm volatile("cp.async.wait_group 0;" ::: "memory"); }

__device__ __forceinline__ void ldsm4(uint32_t& r0, uint32_t& r1, uint32_t& r2, uint32_t& r3,
                                      uint32_t addr) {
    asm volatile("ldmatrix.sync.aligned.m8n8.x4.shared.b16 {%0,%1,%2,%3}, [%4];"
                 : "=r"(r0), "=r"(r1), "=r"(r2), "=r"(r3) : "r"(addr));
}
__device__ __forceinline__ void mma16816(float* c, const uint32_t* a, uint32_t b0, uint32_t b1) {
    asm volatile(
        "mma.sync.aligned.m16n8k16.row.col.f32.bf16.bf16.f32 "
        "{%0,%1,%2,%3}, {%4,%5,%6,%7}, {%8,%9}, {%0,%1,%2,%3};"
        : "+f"(c[0]), "+f"(c[1]), "+f"(c[2]), "+f"(c[3])
        : "r"(a[0]), "r"(a[1]), "r"(a[2]), "r"(a[3]), "r"(b0), "r"(b1));
}

#define SWZ(o) ((o) ^ (((o) >> 3) & 0x70))

// ---------------------------------------------------------------------------
// bf16-split GEMM via mma.sync.  D[m][n'] = sum_k (Ah+Al)[m][k]*(Bh+Bl)[n'][k]
// (fp32 accum, Al*Bl dropped).  A: [M][K] K-major.  B: [N][K] K-major.
// CTA tile 128x128, 8 warps (2 along M x 4 along N), warp tile 64x32,
// K-chunk 64, double-buffered cp.async.
// grid = (N/128, M/128, batch), 256 threads.
// ---------------------------------------------------------------------------
#define STAGE   65536           // 64KB: Ah 16K | Al 16K | Bh 16K | Bl 16K
#define GEMM_SMEM (2 * STAGE)   // 128KB

__device__ __forceinline__ void load_chunk(
    uint32_t dstbase,
    const __nv_bfloat16* __restrict__ Ah, const __nv_bfloat16* __restrict__ Al,
    const __nv_bfloat16* __restrict__ Bh, const __nv_bfloat16* __restrict__ Bl,
    int m0, int n0, int k0, int K, int tid)
{
#pragma unroll
    for (int t = 0; t < 16; t++) {
        int s = tid + t * 256;
        const __nv_bfloat16* srcb;
        uint32_t roff;
        int u, rowbase;
        if (t < 4)       { srcb = Ah; roff = 0;     u = s;        rowbase = m0; }
        else if (t < 8)  { srcb = Al; roff = 16384; u = s - 1024; rowbase = m0; }
        else if (t < 12) { srcb = Bh; roff = 32768; u = s - 2048; rowbase = n0; }
        else             { srcb = Bl; roff = 49152; u = s - 3072; rowbase = n0; }
        int r = u >> 3, c = u & 7;                 // tile row, 16B chunk within 128B row
        const void* src = srcb + (long)(rowbase + r) * K + k0 + c * 8;
        uint32_t dst = dstbase + roff + SWZ((uint32_t)(r * 128 + c * 16));
        cp16(dst, src);
    }
}

__global__ __launch_bounds__(256)
void gemm_mma(const __nv_bfloat16* __restrict__ Ah, const __nv_bfloat16* __restrict__ Al,
              const __nv_bfloat16* __restrict__ Bh, const __nv_bfloat16* __restrict__ Bl,
              float* __restrict__ C, int K, int ldc,
              long sA, long sB, long sC)
{
    extern __shared__ char smem[];
    const uint32_t sb = smem_u32(smem);
    const int tid = threadIdx.x, wid = tid >> 5, lane = tid & 31;
    const int wm = wid & 1, wn = wid >> 1;         // warp grid 2 (M) x 4 (N)
    const int m0 = blockIdx.y * 128, n0 = blockIdx.x * 128;

    Ah += (long)blockIdx.z * sA;  Al += (long)blockIdx.z * sA;
    Bh += (long)blockIdx.z * sB;  Bl += (long)blockIdx.z * sB;
    C  += (long)blockIdx.z * sC;

    float acc[4][4][4];
#pragma unroll
    for (int i = 0; i < 4; i++)
#pragma unroll
        for (int j = 0; j < 4; j++)
#pragma unroll
            for (int q = 0; q < 4; q++) acc[i][j][q] = 0.0f;

    const int nk = K >> 6;

    load_chunk(sb, Ah, Al, Bh, Bl, m0, n0, 0, K, tid);
    cp_commit();

    // Per-lane ldmatrix source coordinates (within a 128-row x 128B tile):
    //   A (m16k16, x4): row = mrow0 + (lane&15), chunk = ks*2 + (lane>>4)
    //   B (n16k16, x4): row = nrow0 + ((lane>>4)<<3) + (lane&7), chunk = ks*2 + ((lane>>3)&1)
    const int a_r = lane & 15;
    const int a_c = lane >> 4;
    const int b_r = ((lane >> 4) << 3) + (lane & 7);
    const int b_c = (lane >> 3) & 1;

    for (int i = 0; i < nk; i++) {
        cp_wait0();
        __syncthreads();
        if (i + 1 < nk) {
            load_chunk(sb + ((i + 1) & 1) * STAGE, Ah, Al, Bh, Bl,
                       m0, n0, (i + 1) << 6, K, tid);
            cp_commit();
        }
        const uint32_t base = sb + (i & 1) * STAGE;

#pragma unroll
        for (int ks = 0; ks < 4; ks++) {
            uint32_t ah[4][4], al[4][4];
#pragma unroll
            for (int mt = 0; mt < 4; mt++) {
                uint32_t o = SWZ((uint32_t)((wm * 64 + mt * 16 + a_r) * 128 + (ks * 2 + a_c) * 16));
                ldsm4(ah[mt][0], ah[mt][1], ah[mt][2], ah[mt][3], base + o);
                ldsm4(al[mt][0], al[mt][1], al[mt][2], al[mt][3], base + 16384 + o);
            }
            uint32_t bh[2][4], bl[2][4];
#pragma unroll
            for (int g = 0; g < 2; g++) {
                uint32_t o = SWZ((uint32_t)((wn * 32 + g * 16 + b_r) * 128 + (ks * 2 + b_c) * 16));
                ldsm4(bh[g][0], bh[g][1], bh[g][2], bh[g][3], base + 32768 + o);
                ldsm4(bl[g][0], bl[g][1], bl[g][2], bl[g][3], base + 49152 + o);
            }
#pragma unroll
            for (int mt = 0; mt < 4; mt++)
#pragma unroll
                for (int nt = 0; nt < 4; nt++) {
                    const int g = nt >> 1, h = (nt & 1) * 2;
                    mma16816(acc[mt][nt], ah[mt], bh[g][h], bh[g][h + 1]);   // Ah*Bh
                    mma16816(acc[mt][nt], ah[mt], bl[g][h], bl[g][h + 1]);   // Ah*Bl
                    mma16816(acc[mt][nt], al[mt], bh[g][h], bh[g][h + 1]);   // Al*Bh
                }
        }
        __syncthreads();
    }

    // Epilogue: standard m16n8 accumulator layout -> fp32 global stores
    const int erow = lane >> 2;
    const int ecol = (lane & 3) * 2;
#pragma unroll
    for (int mt = 0; mt < 4; mt++) {
#pragma unroll
        for (int nt = 0; nt < 4; nt++) {
            int row = m0 + wm * 64 + mt * 16 + erow;
            int col = n0 + wn * 32 + nt * 8 + ecol;
            float2* p0 = (float2*)(C + (long)row * ldc + col);
            float2* p1 = (float2*)(C + (long)(row + 8) * ldc + col);
            *p0 = make_float2(acc[mt][nt][0], acc[mt][nt][1]);
            *p1 = make_float2(acc[mt][nt][2], acc[mt][nt][3]);
        }
    }
}

// ---------------------------------------------------------------------------
// fp32 -> bf16 hi/lo elementwise split
// ---------------------------------------------------------------------------
__global__ void convert_split(const float* __restrict__ in,
                              __nv_bfloat16* __restrict__ oh,
                              __nv_bfloat16* __restrict__ ol, long n)
{
    long i = (long)blockIdx.x * blockDim.x + threadIdx.x;
    if (i >= n) return;
    float f = in[i];
    __nv_bfloat16 h = __float2bfloat16(f);
    __nv_bfloat16 l = __float2bfloat16(f - __bfloat162float(h));
    oh[i] = h;
    ol[i] = l;
}

// ---------------------------------------------------------------------------
// fp32 [R][C] -> bf16 hi/lo transposed [C][R]  (batched over z)
// ---------------------------------------------------------------------------
__global__ __launch_bounds__(256)
void transpose_split(const float* __restrict__ in,
                     __nv_bfloat16* __restrict__ oh, __nv_bfloat16* __restrict__ ol,
                     int R, int C, long si, long so)
{
    __shared__ float t[32][33];
    const float* inb = in + (long)blockIdx.z * si;
    __nv_bfloat16* ohb = oh + (long)blockIdx.z * so;
    __nv_bfloat16* olb = ol + (long)blockIdx.z * so;

    int x = blockIdx.x * 32 + threadIdx.x;
    int y0 = blockIdx.y * 32;
#pragma unroll
    for (int j = threadIdx.y; j < 32; j += 8)
        t[j][threadIdx.x] = inb[(long)(y0 + j) * C + x];
    __syncthreads();
    int ox = blockIdx.y * 32 + threadIdx.x;
    int oy0 = blockIdx.x * 32;
#pragma unroll
    for (int j = threadIdx.y; j < 32; j += 8) {
        float f = t[threadIdx.x][j];
        __nv_bfloat16 h = __float2bfloat16(f);
        __nv_bfloat16 l = __float2bfloat16(f - __bfloat162float(h));
        long o = (long)(oy0 + j) * R + ox;
        ohb[o] = h;
        olb[o] = l;
    }
}

// ---------------------------------------------------------------------------
// Batch-axis softmax (+ 1/32 scale + hard mask), in place over g_scores.
// ---------------------------------------------------------------------------
__global__ void softmax_batch_kernel(const int* __restrict__ mask_from_p,
                                     float* __restrict__ S)
{
    long idx = (long)blockIdx.x * blockDim.x + threadIdx.x;
    if (idx >= SMAT) return;
    const int j = (int)(idx & (NTOK - 1));
    const int i = (int)(idx >> 11);
    const int mf = *mask_from_p;
    const float scale = 0.03125f;

    float s0 = S[idx]            * scale;
    float s1 = S[idx + SMAT]     * scale;
    float s2 = S[idx + 2 * SMAT] * scale;
    float s3 = S[idx + 3 * SMAT] * scale;
    if (i >= mf && j >= mf) s0 = s1 = s2 = s3 = -1.0e12f;
    float m = fmaxf(fmaxf(s0, s1), fmaxf(s2, s3));
    float e0 = expf(s0 - m), e1 = expf(s1 - m), e2 = expf(s2 - m), e3 = expf(s3 - m);
    float inv = 1.0f / (e0 + e1 + e2 + e3);
    S[idx]            = e0 * inv;
    S[idx + SMAT]     = e1 * inv;
    S[idx + 2 * SMAT] = e2 * inv;
    S[idx + 3 * SMAT] = e3 * inv;
}

// ---------------------------------------------------------------------------
// kernel_launch
// ---------------------------------------------------------------------------
extern "C" void kernel_launch(void* const* d_in, const int* in_sizes, int n_in,
                              void* d_out, int out_size)
{
    (void)in_sizes; (void)n_in; (void)out_size;
    const float* x   = (const float*)d_in[0];
    const float* W_q = (const float*)d_in[1];
    const float* W_k = (const float*)d_in[2];
    const float* W_v = (const float*)d_in[3];
    const int* mask_from = (const int*)d_in[4];

    float* out = (float*)d_out;
    float* Q   = out + PER;
    float* K   = out + 2 * PER;
    float* V   = out + 3 * PER;

    float* scores;      cudaGetSymbolAddress((void**)&scores, g_scores);
    __nv_bfloat16* xT;  cudaGetSymbolAddress((void**)&xT, g_xT);
    __nv_bfloat16* W;   cudaGetSymbolAddress((void**)&W, g_W);
    __nv_bfloat16* Qt;  cudaGetSymbolAddress((void**)&Qt, g_Qt);
    __nv_bfloat16* Kt;  cudaGetSymbolAddress((void**)&Kt, g_Kt);
    __nv_bfloat16* Vb;  cudaGetSymbolAddress((void**)&Vb, g_V);
    __nv_bfloat16* At;  cudaGetSymbolAddress((void**)&At, g_At);

    const long ndN = (long)BB * NTOK * DDIM;
    const long w1  = (long)DDIM * DDIM;
    const long w3  = 3 * w1;
    const long at1 = (long)BB * NTOK * NTOK;

    __nv_bfloat16 *xTh = xT, *xTl = xT + ndN;
    __nv_bfloat16 *Wh  = W,  *Wl  = W  + w3;
    __nv_bfloat16 *Qth = Qt, *Qtl = Qt + ndN;
    __nv_bfloat16 *Kth = Kt, *Ktl = Kt + ndN;
    __nv_bfloat16 *Vh  = Vb, *Vl  = Vb + ndN;
    __nv_bfloat16 *Ath = At, *Atl = At + at1;

    // unconditional (idempotent, capture-safe, no static guard)
    cudaFuncSetAttribute(gemm_mma, cudaFuncAttributeMaxDynamicSharedMemorySize, GEMM_SMEM);

    // 1) split W's into stacked [3][d][d] bf16 hi/lo (K-major already)
    {
        int th = 256; long n = w1;
        unsigned bl = (unsigned)((n + th - 1) / th);
        convert_split<<<bl, th>>>(W_q, Wh,          Wl,          n);
        convert_split<<<bl, th>>>(W_k, Wh + w1,     Wl + w1,     n);
        convert_split<<<bl, th>>>(W_v, Wh + 2 * w1, Wl + 2 * w1, n);
    }
    // 2) x [b][d][n] -> xT hi/lo [b][n][d]
    {
        dim3 g(NTOK / 32, DDIM / 32, BB);
        transpose_split<<<g, dim3(32, 8)>>>(x, xTh, xTl, DDIM, NTOK, DN, DN);
    }
    // 3) projections: Q/K/V[m][tok] = sum_e W[m][e] * x[e][tok]
    {
        dim3 g(NTOK / 128, DDIM / 128, BB);
        gemm_mma<<<g, 256, GEMM_SMEM>>>(Wh,          Wl,          xTh, xTl, Q, DDIM, NTOK, 0, DN, DN);
        gemm_mma<<<g, 256, GEMM_SMEM>>>(Wh + w1,     Wl + w1,     xTh, xTl, K, DDIM, NTOK, 0, DN, DN);
        gemm_mma<<<g, 256, GEMM_SMEM>>>(Wh + 2 * w1, Wl + 2 * w1, xTh, xTl, V, DDIM, NTOK, 0, DN, DN);
    }
    // 4) Q,K -> transposed hi/lo; V -> direct hi/lo
    {
        dim3 g(NTOK / 32, DDIM / 32, BB);
        transpose_split<<<g, dim3(32, 8)>>>(Q, Qth, Qtl, DDIM, NTOK, DN, DN);
        transpose_split<<<g, dim3(32, 8)>>>(K, Kth, Ktl, DDIM, NTOK, DN, DN);
        int th = 256; long n = PER;
        convert_split<<<(unsigned)((n + th - 1) / th), th>>>(V, Vh, Vl, n);
    }
    // 5) scores[i][j] = sum_d Qt[i][d] * Kt[j][d]
    {
        dim3 g(NTOK / 128, NTOK / 128, BB);
        gemm_mma<<<g, 256, GEMM_SMEM>>>(Qth, Qtl, Kth, Ktl, scores, DDIM, NTOK, DN, DN, SMAT);
    }
    // 6) batch softmax in place
    {
        int th = 256;
        softmax_batch_kernel<<<(unsigned)((SMAT + th - 1) / th), th>>>(mask_from, scores);
    }
    // 7) attn -> transposed hi/lo
    {
        dim3 g(NTOK / 32, NTOK / 32, BB);
        transpose_split<<<g, dim3(32, 8)>>>(scores, Ath, Atl, NTOK, NTOK, SMAT, SMAT);
    }
    // 8) out[m][tok] = sum_j V[m][j] * attn[j][tok]
    {
        dim3 g(NTOK / 128, DDIM / 128, BB);
        gemm_mma<<<g, 256, GEMM_SMEM>>>(Vh, Vl, Ath, Atl, out, NTOK, NTOK, DN, SMAT, DN);
    }
}

// round 5
// speedup vs baseline: 3.0658x; 1.1705x over previous
#include <cuda_runtime.h>
#include <cuda_bf16.h>
#include <cstdint>

// ---------------------------------------------------------------------------
// Problem constants (fixed by setup_inputs)
// ---------------------------------------------------------------------------
#define BB 4
#define DDIM 1024
#define NTOK 2048
static const long DN   = (long)DDIM * NTOK;        // 2,097,152 elems
static const long PER  = (long)BB * DN;            // 8,388,608 elems per tensor
static const long SMAT = (long)NTOK * NTOK;        // 4,194,304 elems per score mat

// ---------------------------------------------------------------------------
// Static device scratch (allocation-rule-safe).
// ---------------------------------------------------------------------------
__device__ __align__(1024) float         g_scores[(size_t)BB * NTOK * NTOK];      // 64MB
__device__ __align__(1024) __nv_bfloat16 g_xT[2][(size_t)BB * NTOK * DDIM];       // x^T hi/lo [b][n][d]
__device__ __align__(1024) __nv_bfloat16 g_W [2][(size_t)3 * DDIM * DDIM];        // Wq|Wk|Wv hi/lo
__device__ __align__(1024) __nv_bfloat16 g_Qt[2][(size_t)BB * NTOK * DDIM];       // Q^T hi/lo
__device__ __align__(1024) __nv_bfloat16 g_Kt[2][(size_t)BB * NTOK * DDIM];       // K^T hi/lo
__device__ __align__(1024) __nv_bfloat16 g_V [2][(size_t)BB * DDIM * NTOK];       // V hi/lo
__device__ __align__(1024) __nv_bfloat16 g_At[2][(size_t)BB * NTOK * NTOK];       // attn^T hi/lo

// ---------------------------------------------------------------------------
// PTX helpers — sm_80-era only (cp.async, ldmatrix, mma.sync). No tcgen05.
// ---------------------------------------------------------------------------
__device__ __forceinline__ uint32_t smem_u32(const void* p) {
    uint32_t a;
    asm("{ .reg .u64 t; cvta.to.shared.u64 t, %1; cvt.u32.u64 %0, t; }" : "=r"(a) : "l"(p));
    return a;
}
__device__ __forceinline__ void cp16(uint32_t dst, const void* src) {
    asm volatile("cp.async.cg.shared.global [%0], [%1], 16;" :: "r"(dst), "l"(src));
}
__device__ __forceinline__ void cp_commit() { asm volatile("cp.async.commit_group;" ::: "memory"); }
__device__ __forceinline__ void cp_wait0()  { asm volatile("cp.async.wait_group 0;" ::: "memory"); }

__device__ __forceinline__ void ldsm4(uint32_t& r0, uint32_t& r1, uint32_t& r2, uint32_t& r3,
                                      uint32_t addr) {
    asm volatile("ldmatrix.sync.aligned.m8n8.x4.shared.b16 {%0,%1,%2,%3}, [%4];"
                 : "=r"(r0), "=r"(r1), "=r"(r2), "=r"(r3) : "r"(addr));
}
__device__ __forceinline__ void mma16816(float* c, const uint32_t* a, uint32_t b0, uint32_t b1) {
    asm volatile(
        "mma.sync.aligned.m16n8k16.row.col.f32.bf16.bf16.f32 "
        "{%0,%1,%2,%3}, {%4,%5,%6,%7}, {%8,%9}, {%0,%1,%2,%3};"
        : "+f"(c[0]), "+f"(c[1]), "+f"(c[2]), "+f"(c[3])
        : "r"(a[0]), "r"(a[1]), "r"(a[2]), "r"(a[3]), "r"(b0), "r"(b1));
}

#define SWZ(o) ((o) ^ (((o) >> 3) & 0x70))

// ---------------------------------------------------------------------------
// bf16-split GEMM via mma.sync.  D[m][n'] = sum_k (Ah+Al)[m][k]*(Bh+Bl)[n'][k]
// (fp32 accum, Al*Bl dropped).  A: [M][K] K-major.  B: [N][K] K-major.
// CTA tile 256x128, 8 warps (4 along M x 2 along N), warp tile 64x64,
// K-chunk 64, double-buffered cp.async.
// Optional: skip_mf -> early-exit tiles fully inside masked quadrant.
// Optional: Ch/Cl   -> also emit bf16 hi/lo copies of C (same layout).
// grid = (N/128, M/256, batch), 256 threads.
// ---------------------------------------------------------------------------
#define A_BYTES 32768           // 256 rows x 128B (one of hi/lo)
#define B_BYTES 16384           // 128 rows x 128B
#define OFF_AL  32768
#define OFF_BH  65536
#define OFF_BL  81920
#define STAGE   98304           // 96KB per stage
#define GEMM_SMEM (2 * STAGE)   // 192KB

__device__ __forceinline__ void load_chunk(
    uint32_t dstbase,
    const __nv_bfloat16* __restrict__ Ah, const __nv_bfloat16* __restrict__ Al,
    const __nv_bfloat16* __restrict__ Bh, const __nv_bfloat16* __restrict__ Bl,
    int m0, int n0, int k0, int K, int tid)
{
#pragma unroll
    for (int t = 0; t < 24; t++) {
        int s = tid + t * 256;
        const __nv_bfloat16* srcb;
        uint32_t roff;
        int u, rowbase;
        if (t < 8)       { srcb = Ah; roff = 0;      u = s;        rowbase = m0; }
        else if (t < 16) { srcb = Al; roff = OFF_AL; u = s - 2048; rowbase = m0; }
        else if (t < 20) { srcb = Bh; roff = OFF_BH; u = s - 4096; rowbase = n0; }
        else             { srcb = Bl; roff = OFF_BL; u = s - 5120; rowbase = n0; }
        int r = u >> 3, c = u & 7;                 // tile row, 16B chunk within 128B row
        const void* src = srcb + (long)(rowbase + r) * K + k0 + c * 8;
        uint32_t dst = dstbase + roff + SWZ((uint32_t)(r * 128 + c * 16));
        cp16(dst, src);
    }
}

__global__ __launch_bounds__(256, 1)
void gemm_mma(const __nv_bfloat16* __restrict__ Ah, const __nv_bfloat16* __restrict__ Al,
              const __nv_bfloat16* __restrict__ Bh, const __nv_bfloat16* __restrict__ Bl,
              float* __restrict__ C,
              __nv_bfloat16* __restrict__ Ch, __nv_bfloat16* __restrict__ Cl,
              const int* __restrict__ skip_mf,
              int K, int ldc, long sA, long sB, long sC)
{
    extern __shared__ char smem[];
    const uint32_t sb = smem_u32(smem);
    const int tid = threadIdx.x, wid = tid >> 5, lane = tid & 31;
    const int wm = wid >> 1, wn = wid & 1;         // warp grid 4 (M) x 2 (N)
    const int m0 = blockIdx.y * 256, n0 = blockIdx.x * 128;

    if (skip_mf) {
        int mf = *skip_mf;
        if (m0 >= mf && n0 >= mf) return;          // fully-masked scores tile
    }

    Ah += (long)blockIdx.z * sA;  Al += (long)blockIdx.z * sA;
    Bh += (long)blockIdx.z * sB;  Bl += (long)blockIdx.z * sB;
    C  += (long)blockIdx.z * sC;
    if (Ch) { Ch += (long)blockIdx.z * sC; Cl += (long)blockIdx.z * sC; }

    float acc[4][8][4];
#pragma unroll
    for (int i = 0; i < 4; i++)
#pragma unroll
        for (int j = 0; j < 8; j++)
#pragma unroll
            for (int q = 0; q < 4; q++) acc[i][j][q] = 0.0f;

    const int nk = K >> 6;

    load_chunk(sb, Ah, Al, Bh, Bl, m0, n0, 0, K, tid);
    cp_commit();

    const int a_r = lane & 15;
    const int a_c = lane >> 4;
    const int b_r = ((lane >> 4) << 3) + (lane & 7);
    const int b_c = (lane >> 3) & 1;

    for (int i = 0; i < nk; i++) {
        cp_wait0();
        __syncthreads();
        if (i + 1 < nk) {
            load_chunk(sb + ((i + 1) & 1) * STAGE, Ah, Al, Bh, Bl,
                       m0, n0, (i + 1) << 6, K, tid);
            cp_commit();
        }
        const uint32_t base = sb + (i & 1) * STAGE;

#pragma unroll
        for (int ks = 0; ks < 4; ks++) {
            uint32_t ah[4][4], al[4][4];
#pragma unroll
            for (int mt = 0; mt < 4; mt++) {
                uint32_t o = SWZ((uint32_t)((wm * 64 + mt * 16 + a_r) * 128 + (ks * 2 + a_c) * 16));
                ldsm4(ah[mt][0], ah[mt][1], ah[mt][2], ah[mt][3], base + o);
                ldsm4(al[mt][0], al[mt][1], al[mt][2], al[mt][3], base + OFF_AL + o);
            }
#pragma unroll
            for (int g = 0; g < 4; g++) {          // 4 n16 groups -> warp N=64
                uint32_t bh[4], bl[4];
                uint32_t o = SWZ((uint32_t)((wn * 64 + g * 16 + b_r) * 128 + (ks * 2 + b_c) * 16));
                ldsm4(bh[0], bh[1], bh[2], bh[3], base + OFF_BH + o);
                ldsm4(bl[0], bl[1], bl[2], bl[3], base + OFF_BL + o);
#pragma unroll
                for (int mt = 0; mt < 4; mt++)
#pragma unroll
                    for (int h2 = 0; h2 < 2; h2++) {
                        const int nt = g * 2 + h2;
                        mma16816(acc[mt][nt], ah[mt], bh[h2 * 2], bh[h2 * 2 + 1]);   // Ah*Bh
                        mma16816(acc[mt][nt], ah[mt], bl[h2 * 2], bl[h2 * 2 + 1]);   // Ah*Bl
                        mma16816(acc[mt][nt], al[mt], bh[h2 * 2], bh[h2 * 2 + 1]);   // Al*Bh
                    }
            }
        }
    }

    // Epilogue: fp32 stores (+ optional bf16 hi/lo copies)
    const int erow = lane >> 2;
    const int ecol = (lane & 3) * 2;
#pragma unroll
    for (int mt = 0; mt < 4; mt++) {
#pragma unroll
        for (int nt = 0; nt < 8; nt++) {
            int row = m0 + wm * 64 + mt * 16 + erow;
            int col = n0 + wn * 64 + nt * 8 + ecol;
            long o0 = (long)row * ldc + col;
            long o1 = (long)(row + 8) * ldc + col;
            *(float2*)(C + o0) = make_float2(acc[mt][nt][0], acc[mt][nt][1]);
            *(float2*)(C + o1) = make_float2(acc[mt][nt][2], acc[mt][nt][3]);
            if (Ch) {
                float a0 = acc[mt][nt][0], a1 = acc[mt][nt][1];
                float a2 = acc[mt][nt][2], a3 = acc[mt][nt][3];
                __nv_bfloat16 h0 = __float2bfloat16(a0), h1 = __float2bfloat16(a1);
                __nv_bfloat16 h2 = __float2bfloat16(a2), h3 = __float2bfloat16(a3);
                *(__nv_bfloat162*)(Ch + o0) = __halves2bfloat162(h0, h1);
                *(__nv_bfloat162*)(Ch + o1) = __halves2bfloat162(h2, h3);
                *(__nv_bfloat162*)(Cl + o0) = __halves2bfloat162(
                    __float2bfloat16(a0 - __bfloat162float(h0)),
                    __float2bfloat16(a1 - __bfloat162float(h1)));
                *(__nv_bfloat162*)(Cl + o1) = __halves2bfloat162(
                    __float2bfloat16(a2 - __bfloat162float(h2)),
                    __float2bfloat16(a3 - __bfloat162float(h3)));
            }
        }
    }
}

// ---------------------------------------------------------------------------
// fp32 -> bf16 hi/lo elementwise split
// ---------------------------------------------------------------------------
__global__ void convert_split(const float* __restrict__ in,
                              __nv_bfloat16* __restrict__ oh,
                              __nv_bfloat16* __restrict__ ol, long n)
{
    long i = (long)blockIdx.x * blockDim.x + threadIdx.x;
    if (i >= n) return;
    float f = in[i];
    __nv_bfloat16 h = __float2bfloat16(f);
    __nv_bfloat16 l = __float2bfloat16(f - __bfloat162float(h));
    oh[i] = h;
    ol[i] = l;
}

// ---------------------------------------------------------------------------
// fp32 [R][C] -> bf16 hi/lo transposed [C][R]  (batched over z)
// ---------------------------------------------------------------------------
__global__ __launch_bounds__(256)
void transpose_split(const float* __restrict__ in,
                     __nv_bfloat16* __restrict__ oh, __nv_bfloat16* __restrict__ ol,
                     int R, int C, long si, long so)
{
    __shared__ float t[32][33];
    const float* inb = in + (long)blockIdx.z * si;
    __nv_bfloat16* ohb = oh + (long)blockIdx.z * so;
    __nv_bfloat16* olb = ol + (long)blockIdx.z * so;

    int x = blockIdx.x * 32 + threadIdx.x;
    int y0 = blockIdx.y * 32;
#pragma unroll
    for (int j = threadIdx.y; j < 32; j += 8)
        t[j][threadIdx.x] = inb[(long)(y0 + j) * C + x];
    __syncthreads();
    int ox = blockIdx.y * 32 + threadIdx.x;
    int oy0 = blockIdx.x * 32;
#pragma unroll
    for (int j = threadIdx.y; j < 32; j += 8) {
        float f = t[threadIdx.x][j];
        __nv_bfloat16 h = __float2bfloat16(f);
        __nv_bfloat16 l = __float2bfloat16(f - __bfloat162float(h));
        long o = (long)(oy0 + j) * R + ox;
        ohb[o] = h;
        olb[o] = l;
    }
}

// ---------------------------------------------------------------------------
// Fused: batch-axis softmax (+1/32 scale + hard mask) on fp32 scores,
// then TRANSPOSED bf16 hi/lo write: At[b][m][n] = attn[b][n][m].
// grid (NTOK/32, NTOK/32), block (32, 8).
// ---------------------------------------------------------------------------
__global__ __launch_bounds__(256)
void softmax_t_kernel(const int* __restrict__ mask_from_p,
                      const float* __restrict__ S,
                      __nv_bfloat16* __restrict__ Ath,
                      __nv_bfloat16* __restrict__ Atl)
{
    __shared__ float a4[BB][32][33];
    const int mf = *mask_from_p;
    const int i0 = blockIdx.y * 32;                // n (first attn index)
    const int j0 = blockIdx.x * 32;                // m (second attn index)
    const int tx = threadIdx.x, ty = threadIdx.y;
    const float scale = 0.03125f;

#pragma unroll
    for (int ii = 0; ii < 4; ii++) {
        int i = i0 + ty + ii * 8;
        int j = j0 + tx;
        long idx = (long)i * NTOK + j;
        float s0 = S[idx]            * scale;
        float s1 = S[idx + SMAT]     * scale;
        float s2 = S[idx + 2 * SMAT] * scale;
        float s3 = S[idx + 3 * SMAT] * scale;
        float a0, a1, a2, a3;
        if (i >= mf && j >= mf) {
            a0 = a1 = a2 = a3 = 0.25f;
        } else {
            float m = fmaxf(fmaxf(s0, s1), fmaxf(s2, s3));
            float e0 = expf(s0 - m), e1 = expf(s1 - m);
            float e2 = expf(s2 - m), e3 = expf(s3 - m);
            float inv = 1.0f / (e0 + e1 + e2 + e3);
            a0 = e0 * inv; a1 = e1 * inv; a2 = e2 * inv; a3 = e3 * inv;
        }
        a4[0][ty + ii * 8][tx] = a0;
        a4[1][ty + ii * 8][tx] = a1;
        a4[2][ty + ii * 8][tx] = a2;
        a4[3][ty + ii * 8][tx] = a3;
    }
    __syncthreads();

#pragma unroll
    for (int jj = 0; jj < 4; jj++) {
        int jm = j0 + ty + jj * 8;                 // output row (m)
        int in = i0 + tx;                          // output col (n)
#pragma unroll
        for (int b = 0; b < BB; b++) {
            float v = a4[b][tx][ty + jj * 8];
            __nv_bfloat16 h = __float2bfloat16(v);
            __nv_bfloat16 l = __float2bfloat16(v - __bfloat162float(h));
            long o = (long)b * SMAT + (long)jm * NTOK + in;
            Ath[o] = h;
            Atl[o] = l;
        }
    }
}

// ---------------------------------------------------------------------------
// kernel_launch
// ---------------------------------------------------------------------------
extern "C" void kernel_launch(void* const* d_in, const int* in_sizes, int n_in,
                              void* d_out, int out_size)
{
    (void)in_sizes; (void)n_in; (void)out_size;
    const float* x   = (const float*)d_in[0];
    const float* W_q = (const float*)d_in[1];
    const float* W_k = (const float*)d_in[2];
    const float* W_v = (const float*)d_in[3];
    const int* mask_from = (const int*)d_in[4];

    float* out = (float*)d_out;
    float* Q   = out + PER;
    float* K   = out + 2 * PER;
    float* V   = out + 3 * PER;

    float* scores;      cudaGetSymbolAddress((void**)&scores, g_scores);
    __nv_bfloat16* xT;  cudaGetSymbolAddress((void**)&xT, g_xT);
    __nv_bfloat16* W;   cudaGetSymbolAddress((void**)&W, g_W);
    __nv_bfloat16* Qt;  cudaGetSymbolAddress((void**)&Qt, g_Qt);
    __nv_bfloat16* Kt;  cudaGetSymbolAddress((void**)&Kt, g_Kt);
    __nv_bfloat16* Vb;  cudaGetSymbolAddress((void**)&Vb, g_V);
    __nv_bfloat16* At;  cudaGetSymbolAddress((void**)&At, g_At);

    const long ndN = (long)BB * NTOK * DDIM;
    const long w1  = (long)DDIM * DDIM;
    const long w3  = 3 * w1;
    const long at1 = (long)BB * NTOK * NTOK;

    __nv_bfloat16 *xTh = xT, *xTl = xT + ndN;
    __nv_bfloat16 *Wh  = W,  *Wl  = W  + w3;
    __nv_bfloat16 *Qth = Qt, *Qtl = Qt + ndN;
    __nv_bfloat16 *Kth = Kt, *Ktl = Kt + ndN;
    __nv_bfloat16 *Vh  = Vb, *Vl  = Vb + ndN;
    __nv_bfloat16 *Ath = At, *Atl = At + at1;

    cudaFuncSetAttribute(gemm_mma, cudaFuncAttributeMaxDynamicSharedMemorySize, GEMM_SMEM);

    // 1) split W's into stacked [3][d][d] bf16 hi/lo
    {
        int th = 256; long n = w1;
        unsigned bl = (unsigned)((n + th - 1) / th);
        convert_split<<<bl, th>>>(W_q, Wh,          Wl,          n);
        convert_split<<<bl, th>>>(W_k, Wh + w1,     Wl + w1,     n);
        convert_split<<<bl, th>>>(W_v, Wh + 2 * w1, Wl + 2 * w1, n);
    }
    // 2) x [b][d][n] -> xT hi/lo [b][n][d]
    {
        dim3 g(NTOK / 32, DDIM / 32, BB);
        transpose_split<<<g, dim3(32, 8)>>>(x, xTh, xTl, DDIM, NTOK, DN, DN);
    }
    // 3) projections (V also emits bf16 hi/lo in epilogue)
    {
        dim3 g(NTOK / 128, DDIM / 256, BB);
        gemm_mma<<<g, 256, GEMM_SMEM>>>(Wh,          Wl,          xTh, xTl, Q,
                                        nullptr, nullptr, nullptr, DDIM, NTOK, 0, DN, DN);
        gemm_mma<<<g, 256, GEMM_SMEM>>>(Wh + w1,     Wl + w1,     xTh, xTl, K,
                                        nullptr, nullptr, nullptr, DDIM, NTOK, 0, DN, DN);
        gemm_mma<<<g, 256, GEMM_SMEM>>>(Wh + 2 * w1, Wl + 2 * w1, xTh, xTl, V,
                                        Vh, Vl, nullptr, DDIM, NTOK, 0, DN, DN);
    }
    // 4) Q,K -> transposed hi/lo
    {
        dim3 g(NTOK / 32, DDIM / 32, BB);
        transpose_split<<<g, dim3(32, 8)>>>(Q, Qth, Qtl, DDIM, NTOK, DN, DN);
        transpose_split<<<g, dim3(32, 8)>>>(K, Kth, Ktl, DDIM, NTOK, DN, DN);
    }
    // 5) scores = Qt * Kt^T (skip fully-masked tiles)
    {
        dim3 g(NTOK / 128, NTOK / 256, BB);
        gemm_mma<<<g, 256, GEMM_SMEM>>>(Qth, Qtl, Kth, Ktl, scores,
                                        nullptr, nullptr, mask_from, DDIM, NTOK, DN, DN, SMAT);
    }
    // 6) fused batch softmax + transpose + bf16 split -> At hi/lo
    {
        dim3 g(NTOK / 32, NTOK / 32);
        softmax_t_kernel<<<g, dim3(32, 8)>>>(mask_from, scores, Ath, Atl);
    }
    // 7) out = V * attn
    {
        dim3 g(NTOK / 128, DDIM / 256, BB);
        gemm_mma<<<g, 256, GEMM_SMEM>>>(Vh, Vl, Ath, Atl, out,
                                        nullptr, nullptr, nullptr, NTOK, NTOK, DN, SMAT, DN);
    }
}